// round 16
// baseline (speedup 1.0000x reference)
#include <cuda_runtime.h>
#include <cuda_fp16.h>
#include <math.h>
#include <stdint.h>

// ---------------------------------------------------------------------------
// B=8, L=1024, D=1024, H=16, DK=64  (BH=128, M=8192)
// fp16 m16n8k16 everywhere. Rank-64 bias (G=C^T C, M=C^T V) fp16.
// Max-free softmax; register-direct p repack. 4-stage attn/out-proj pipeline
// at 2-batch granularity (attn chunk i -> out-proj rows i*2048..+2047 on s2).
// ---------------------------------------------------------------------------
__device__ __half g_qin_h[8388608];
__device__ __half g_wqt_h[1048576];
__device__ __half g_wkt_h[1048576];
__device__ __half g_wvt_h[1048576];
__device__ __half g_wot_h[1048576];
__device__ __half g_qh[8388608];
__device__ __half g_kh[8388608];
__device__ __half g_vh[8388608];
__device__ __half g_ch[8388608];
__device__ __half g_cbh[8388608];
__device__ __half g_mh[8388608];
__device__ __half g_Gh[524288];
__device__ __half g_Mh[524288];

// ---------------------------------------------------------------------------
__device__ __forceinline__ uint32_t f2tf(float f) {
    uint32_t r; asm("cvt.rna.tf32.f32 %0, %1;" : "=r"(r) : "f"(f)); return r;
}
__device__ __forceinline__ void ldm4(uint32_t* r, const void* p) {
    uint32_t a = (uint32_t)__cvta_generic_to_shared(p);
    asm volatile("ldmatrix.sync.aligned.m8n8.x4.shared.b16 {%0,%1,%2,%3}, [%4];"
        : "=r"(r[0]), "=r"(r[1]), "=r"(r[2]), "=r"(r[3]) : "r"(a));
}
__device__ __forceinline__ void ldm4t(uint32_t* r, const void* p) {
    uint32_t a = (uint32_t)__cvta_generic_to_shared(p);
    asm volatile("ldmatrix.sync.aligned.m8n8.x4.trans.shared.b16 {%0,%1,%2,%3}, [%4];"
        : "=r"(r[0]), "=r"(r[1]), "=r"(r[2]), "=r"(r[3]) : "r"(a));
}
__device__ __forceinline__ void mma8(float* c, const uint32_t* a, uint32_t b0, uint32_t b1) {
    asm volatile("mma.sync.aligned.m16n8k8.row.col.f32.tf32.tf32.f32 "
        "{%0,%1,%2,%3},{%4,%5,%6,%7},{%8,%9},{%0,%1,%2,%3};"
        : "+f"(c[0]), "+f"(c[1]), "+f"(c[2]), "+f"(c[3])
        : "r"(a[0]), "r"(a[1]), "r"(a[2]), "r"(a[3]), "r"(b0), "r"(b1));
}
__device__ __forceinline__ void mma16h(float* c, const uint32_t* a, uint32_t b0, uint32_t b1) {
    asm volatile("mma.sync.aligned.m16n8k16.row.col.f32.f16.f16.f32 "
        "{%0,%1,%2,%3},{%4,%5,%6,%7},{%8,%9},{%0,%1,%2,%3};"
        : "+f"(c[0]), "+f"(c[1]), "+f"(c[2]), "+f"(c[3])
        : "r"(a[0]), "r"(a[1]), "r"(a[2]), "r"(a[3]), "r"(b0), "r"(b1));
}
__device__ __forceinline__ void cpa16(void* s, const void* g) {
    uint32_t a = (uint32_t)__cvta_generic_to_shared(s);
    asm volatile("cp.async.cg.shared.global [%0], [%1], 16;" :: "r"(a), "l"(g));
}
#define CPA_COMMIT() asm volatile("cp.async.commit_group;" ::: "memory")
#define CPA_WAIT1()  asm volatile("cp.async.wait_group 1;" ::: "memory")
#define CPA_WAIT0()  asm volatile("cp.async.wait_group 0;" ::: "memory")

// ---------------------------------------------------------------------------
__global__ __launch_bounds__(256) void cvt_half(
    const float* __restrict__ src, __half* __restrict__ dst, int n4)
{
    int i = blockIdx.x * 256 + threadIdx.x;
    if (i < n4) {
        float4 v = ((const float4*)src)[i];
        __half2 a = __floats2half2_rn(v.x, v.y);
        __half2 b = __floats2half2_rn(v.z, v.w);
        uint2 o;
        o.x = *(uint32_t*)&a; o.y = *(uint32_t*)&b;
        *(uint2*)(dst + (size_t)i * 4) = o;
    }
}
__global__ __launch_bounds__(256) void transpose_cvt_h4(
    const float* __restrict__ s0, const float* __restrict__ s1,
    const float* __restrict__ s2, const float* __restrict__ s3)
{
    __shared__ float t[32][33];
    const int z = blockIdx.z;
    const float* src = (z == 0) ? s0 : (z == 1) ? s1 : (z == 2) ? s2 : s3;
    __half* dst = (z == 0) ? g_wqt_h : (z == 1) ? g_wkt_h : (z == 2) ? g_wvt_h : g_wot_h;
    int bk = blockIdx.x << 5, bn = blockIdx.y << 5;
    int x = threadIdx.x & 31, y = threadIdx.x >> 5;
#pragma unroll
    for (int j = 0; j < 32; j += 8)
        t[y + j][x] = src[(size_t)(bk + y + j) * 1024 + bn + x];
    __syncthreads();
#pragma unroll
    for (int j = 0; j < 32; j += 8)
        dst[(size_t)(bn + y + j) * 1024 + bk + x] = __float2half_rn(t[x][y + j]);
}

// ---------------------------------------------------------------------------
// fp16 GEMM 128x128xBK32 (m16n8k16), cp.async 3-stage pipeline.
// ---------------------------------------------------------------------------
#define GEMM_SMEM_BYTES 61440

template <int QKV>
__global__ __launch_bounds__(256) void gemm_h(
    const __half* __restrict__ A,
    const float* __restrict__ bias_q, const float* __restrict__ bias_k,
    const float* __restrict__ bias_v, float* __restrict__ Cout, int ybase)
{
    extern __shared__ __half gsm[];

    const int tid = threadIdx.x;
    const int lane = tid & 31, w = tid >> 5;
    const int r0 = (blockIdx.y + ybase) << 7, c0 = blockIdx.x << 7;
    const int dst = QKV ? (int)blockIdx.z : 3;
    const __half* Wt = QKV
        ? ((dst == 0) ? g_wqt_h : (dst == 1) ? g_wkt_h : g_wvt_h)
        : g_wot_h;
    const float* bias = QKV
        ? ((dst == 0) ? bias_q : (dst == 1) ? bias_k : bias_v)
        : bias_q;

    const int mwarp = (w >> 2) * 64, nwarp = (w & 3) * 32;
    const int lrow = lane & 15;
    const int lcol8 = (lane >> 4) << 3;
    const int bn_ = lane >> 2;
    const int bk_ = (lane & 3) << 1;

    const int ld_row0 = tid >> 2, ld_off = (tid & 3) << 3;
    const int ld_row1 = (tid + 256) >> 2;

    float acc[4][4][4] = {};

    auto ld_stage = [&](int kt, int s) {
        __half* As = &gsm[s * 10240];
        __half* Bs = As + 5120;
        const __half* ag = A + (size_t)r0 * 1024 + (kt << 5);
        const __half* bg = Wt + (size_t)c0 * 1024 + (kt << 5);
        cpa16(&As[ld_row0 * 40 + ld_off], ag + (size_t)ld_row0 * 1024 + ld_off);
        cpa16(&As[ld_row1 * 40 + ld_off], ag + (size_t)ld_row1 * 1024 + ld_off);
        cpa16(&Bs[ld_row0 * 40 + ld_off], bg + (size_t)ld_row0 * 1024 + ld_off);
        cpa16(&Bs[ld_row1 * 40 + ld_off], bg + (size_t)ld_row1 * 1024 + ld_off);
    };

    ld_stage(0, 0); CPA_COMMIT();
    ld_stage(1, 1); CPA_COMMIT();

#pragma unroll 1
    for (int kt = 0; kt < 32; kt++) {
        if (kt + 2 < 32) { CPA_WAIT1(); } else { CPA_WAIT0(); }
        __syncthreads();
        if (kt + 2 < 32) { ld_stage(kt + 2, (kt + 2) % 3); CPA_COMMIT(); }

        const __half* As = &gsm[(kt % 3) * 10240];
        const __half* Bs = As + 5120;
#pragma unroll
        for (int ks = 0; ks < 2; ks++) {
            const int kof = ks << 4;
            uint32_t afr[4][4];
#pragma unroll
            for (int mt = 0; mt < 4; mt++)
                ldm4(afr[mt], &As[(mwarp + mt * 16 + lrow) * 40 + kof + lcol8]);
            uint32_t b0r[4], b1r[4];
#pragma unroll
            for (int nt = 0; nt < 4; nt++) {
                const __half* bp = &Bs[(nwarp + nt * 8 + bn_) * 40 + kof + bk_];
                b0r[nt] = *(const uint32_t*)bp;
                b1r[nt] = *(const uint32_t*)(bp + 8);
            }
#pragma unroll
            for (int mt = 0; mt < 4; mt++)
#pragma unroll
                for (int nt = 0; nt < 4; nt++)
                    mma16h(acc[mt][nt], afr[mt], b0r[nt], b1r[nt]);
        }
    }

    __half* Hsplit = (dst == 0) ? g_qh : (dst == 1) ? g_kh : g_vh;
    const int rl = lane >> 2, cl = (lane & 3) << 1;
#pragma unroll
    for (int mt = 0; mt < 4; mt++)
#pragma unroll
        for (int nt = 0; nt < 4; nt++) {
            int row = r0 + mwarp + mt * 16 + rl;
            int col = c0 + nwarp + nt * 8 + cl;
            float bv0 = bias[col], bv1 = bias[col + 1];
            float v00 = acc[mt][nt][0] + bv0, v01 = acc[mt][nt][1] + bv1;
            float v10 = acc[mt][nt][2] + bv0, v11 = acc[mt][nt][3] + bv1;
            if (QKV) {
                int h = col >> 6, dk = col & 63;
                int b0i = row >> 10, l0 = row & 1023;
                int b1i = (row + 8) >> 10, l1 = (row + 8) & 1023;
                size_t i0 = (((size_t)((b0i << 4) + h)) << 16) + ((size_t)l0 << 6) + dk;
                size_t i1 = (((size_t)((b1i << 4) + h)) << 16) + ((size_t)l1 << 6) + dk;
                *(__half2*)&Hsplit[i0] = __floats2half2_rn(v00, v01);
                *(__half2*)&Hsplit[i1] = __floats2half2_rn(v10, v11);
            } else {
                *(float2*)&Cout[(size_t)row * 1024 + col] = make_float2(v00, v01);
                *(float2*)&Cout[(size_t)(row + 8) * 1024 + col] = make_float2(v10, v11);
            }
        }
}

// ---------------------------------------------------------------------------
// LayerNorm(ctx -> heads) -> g_ch (half) ; g_cbh via tf32 mma.
// ---------------------------------------------------------------------------
__global__ __launch_bounds__(128) void ln_bilinear_kernel(
    const float* __restrict__ ctx, const float* __restrict__ bil,
    const float* __restrict__ gamma, const float* __restrict__ beta)
{
    __shared__ uint32_t cs[64 * 68];
    __shared__ uint32_t bls[64 * 68];
    const int tid = threadIdx.x, lane = tid & 31, w = tid >> 5;

    for (int i = tid; i < 1024; i += 128) {
        int idx4 = i << 2;
        int row = idx4 >> 6, col = idx4 & 63;
        float4 v = *(const float4*)(bil + idx4);
        uint4 o;
        o.x = f2tf(v.x); o.y = f2tf(v.y); o.z = f2tf(v.z); o.w = f2tf(v.w);
        *(uint4*)&bls[row * 68 + col] = o;
    }

    const float g0 = gamma[lane], g1 = gamma[lane + 32];
    const float be0 = beta[lane], be1 = beta[lane + 32];

#pragma unroll 1
    for (int r = 0; r < 16; r++) {
        int rloc = w * 16 + r;
        int rid = blockIdx.x * 64 + rloc;
        int bh = rid >> 10, l = rid & 1023;
        int b = bh >> 4, h = bh & 15;
        const float* x = ctx + ((size_t)((b << 10) + l) << 10) + (h << 6);

        float v0 = x[lane], v1 = x[lane + 32];
        float s = v0 + v1;
#pragma unroll
        for (int o = 16; o > 0; o >>= 1) s += __shfl_xor_sync(0xffffffffu, s, o);
        float mu = s * (1.f / 64.f);
        float d0 = v0 - mu, d1 = v1 - mu;
        float vs = d0 * d0 + d1 * d1;
#pragma unroll
        for (int o = 16; o > 0; o >>= 1) vs += __shfl_xor_sync(0xffffffffu, vs, o);
        float inv = rsqrtf(vs * (1.f / 64.f) + 1e-5f);

        float c0 = d0 * inv * g0 + be0;
        float c1 = d1 * inv * g1 + be1;
        g_ch[((size_t)rid << 6) + lane] = __float2half_rn(c0);
        g_ch[((size_t)rid << 6) + lane + 32] = __float2half_rn(c1);
        cs[rloc * 68 + lane] = f2tf(c0);
        cs[rloc * 68 + lane + 32] = f2tf(c1);
    }
    __syncthreads();

    const int aoff = ((lane & 7) + ((lane >> 3) & 1) * 8) * 68 + ((lane >> 4) << 2);
    const int bV = (lane & 3) * 68 + (lane >> 2);
    float acc[8][4] = {};
#pragma unroll
    for (int k0 = 0; k0 < 64; k0 += 8) {
        uint32_t af[4];
        ldm4(af, &cs[(w * 16) * 68 + k0 + aoff]);
#pragma unroll
        for (int nt = 0; nt < 8; nt++) {
            uint32_t b0 = bls[k0 * 68 + bV + nt * 8];
            uint32_t b1 = bls[(k0 + 4) * 68 + bV + nt * 8];
            mma8(acc[nt], af, b0, b1);
        }
    }
    const int r0 = w * 16 + (lane >> 2);
    const size_t rid0 = (size_t)(blockIdx.x * 64 + r0);
    const int cbase = (lane & 3) << 1;
#pragma unroll
    for (int nt = 0; nt < 8; nt++) {
        int dk = nt * 8 + cbase;
        *(__half2*)&g_cbh[(rid0 << 6) + dk] = __floats2half2_rn(acc[nt][0], acc[nt][1]);
        *(__half2*)&g_cbh[((rid0 + 8) << 6) + dk] = __floats2half2_rn(acc[nt][2], acc[nt][3]);
    }
}

// ---------------------------------------------------------------------------
// Per-head Gram matrices (fp16): G = C^T C, M = C^T V. One block/bh.
// ---------------------------------------------------------------------------
__global__ __launch_bounds__(256) void gram_kernel()
{
    __shared__ __half cs[64 * 72];
    __shared__ __half vs[64 * 72];
    const int bh = blockIdx.x;
    const __half* cg = g_ch + ((size_t)bh << 16);
    const __half* vg = g_vh + ((size_t)bh << 16);

    const int tid = threadIdx.x, lane = tid & 31, w = tid >> 5;
    const int m0 = (w & 3) * 16, nh = (w >> 2) * 32;
    const int l8 = lane & 7, grp = lane >> 3;
    const int a_trow = ((grp >> 1) << 3) + l8;
    const int a_tcol = m0 + ((grp & 1) << 3);
    const int b_trow = ((grp & 1) << 3) + l8;
    const int b_tcol = (grp >> 1) << 3;

    float accG[4][4] = {}, accM[4][4] = {};

#pragma unroll 1
    for (int lc = 0; lc < 16; lc++) {
        __syncthreads();
#pragma unroll
        for (int t = 0; t < 2; t++) {
            int i = tid + t * 256;
            int row = i >> 3, sub = (i & 7) << 3;
            *(uint4*)&cs[row * 72 + sub] =
                *(const uint4*)(cg + ((lc << 6) + row) * 64 + sub);
            *(uint4*)&vs[row * 72 + sub] =
                *(const uint4*)(vg + ((lc << 6) + row) * 64 + sub);
        }
        __syncthreads();
#pragma unroll
        for (int kc = 0; kc < 4; kc++) {
            const int k0 = kc << 4;
            uint32_t af[4];
            ldm4t(af, &cs[(k0 + a_trow) * 72 + a_tcol]);
#pragma unroll
            for (int ng = 0; ng < 2; ng++) {
                const int n0 = nh + (ng << 4);
                uint32_t gb[4];
                ldm4t(gb, &cs[(k0 + b_trow) * 72 + n0 + b_tcol]);
                mma16h(accG[ng * 2], af, gb[0], gb[1]);
                mma16h(accG[ng * 2 + 1], af, gb[2], gb[3]);
                uint32_t mb[4];
                ldm4t(mb, &vs[(k0 + b_trow) * 72 + n0 + b_tcol]);
                mma16h(accM[ng * 2], af, mb[0], mb[1]);
                mma16h(accM[ng * 2 + 1], af, mb[2], mb[3]);
            }
        }
    }

    __half* Gg = g_Gh + (bh << 12);
    __half* Mg = g_Mh + (bh << 12);
    const int rl = lane >> 2, cl = (lane & 3) << 1;
#pragma unroll
    for (int nt = 0; nt < 4; nt++) {
        int row = m0 + rl, col = nh + nt * 8 + cl;
        *(__half2*)&Gg[row * 64 + col] = __floats2half2_rn(accG[nt][0], accG[nt][1]);
        *(__half2*)&Gg[(row + 8) * 64 + col] = __floats2half2_rn(accG[nt][2], accG[nt][3]);
        *(__half2*)&Mg[row * 64 + col] = __floats2half2_rn(accM[nt][0], accM[nt][1]);
        *(__half2*)&Mg[(row + 8) * 64 + col] = __floats2half2_rn(accM[nt][2], accM[nt][3]);
    }
}

// ---------------------------------------------------------------------------
// Fused attention: fp16, cp.async double-buffered, max-free softmax,
// register-direct p repack.
// ---------------------------------------------------------------------------
#define HAQ   0
#define HACB  9216
#define HG    18432
#define HM    23040
#define HBS   27648
#define HSTG  13824
#define H_TOT 55296
#define SM_TOTAL_BYTES (H_TOT * 2)   // 110592

__global__ __launch_bounds__(256) void fused_attn(
    const float* __restrict__ scale_p, const float* __restrict__ bscale_p, int bh0)
{
    extern __shared__ __half smh[];

    const int qt = (int)(gridDim.x - 1 - blockIdx.x);
    const int bh = bh0 + blockIdx.y;
    const int tid = threadIdx.x, lane = tid & 31, w = tid >> 5;

    const __half* qg = g_qh + ((size_t)bh << 16) + ((size_t)(qt << 7) << 6);
    const __half* cbg = g_cbh + ((size_t)bh << 16) + ((size_t)(qt << 7) << 6);
    const __half* kg = g_kh + ((size_t)bh << 16);
    const __half* cg = g_ch + ((size_t)bh << 16);
    const __half* vg = g_vh + ((size_t)bh << 16);
    const __half* Gg = g_Gh + (bh << 12);
    const __half* Mg = g_Mh + (bh << 12);

    const float sc2 = (*scale_p) * 1.4426950408889634f;
    const float bs = *bscale_p;
    const int ktmax = 2 * qt + 2;

    auto ld_stage = [&](int kt, int s) {
        __half* base = &smh[HBS + s * HSTG];
#pragma unroll
        for (int t = 0; t < 2; t++) {
            int i = tid + t * 256;
            int key = i >> 3, sub = (i & 7) << 3;
            cpa16(&base[key * 72 + sub], kg + ((kt << 6) + key) * 64 + sub);
            cpa16(&base[4608 + key * 72 + sub], cg + ((kt << 6) + key) * 64 + sub);
            cpa16(&base[9216 + key * 72 + sub], vg + ((kt << 6) + key) * 64 + sub);
        }
    };

    ld_stage(0, 0);
    CPA_COMMIT();

#pragma unroll
    for (int t = 0; t < 4; t++) {
        int i = tid + t * 256;
        int row = i >> 3, sub = (i & 7) << 3;
        *(uint4*)&smh[HAQ + row * 72 + sub] = *(const uint4*)(qg + row * 64 + sub);
    }
#pragma unroll
    for (int t = 0; t < 4; t++) {
        int i = tid + t * 256;
        int row = i >> 3, sub = (i & 7) << 3;
        *(uint4*)&smh[HACB + row * 72 + sub] = *(const uint4*)(cbg + row * 64 + sub);
    }
#pragma unroll
    for (int t = 0; t < 2; t++) {
        int i = tid + t * 256;
        int row = i >> 3, sub = (i & 7) << 3;
        *(uint4*)&smh[HG + row * 72 + sub] = *(const uint4*)(Gg + row * 64 + sub);
        *(uint4*)&smh[HM + row * 72 + sub] = *(const uint4*)(Mg + row * 64 + sub);
    }
    __syncthreads();

    const int r0 = w * 16 + (lane >> 2);
    const int qrow0 = (qt << 7) + r0;
    const int qrow1 = qrow0 + 8;
    const int cbase = (lane & 3) << 1;

    const int haoff = (w * 16 + (lane & 15)) * 72 + ((lane >> 4) << 3);
    const int hbn = lane >> 2;
    const int hbk = (lane & 3) << 1;
    const int l8 = lane & 7, grp = lane >> 3;
    const int trow_off = ((grp & 1) << 3) + l8;
    const int tcol_off = (grp >> 1) << 3;

    float bvv[8][4] = {};
    float bsq0 = 0.f, bsq1 = 0.f;
    {
        float cbG[8][4] = {};
#pragma unroll
        for (int kc = 0; kc < 4; kc++) {
            const int k0 = kc << 4;
            uint32_t af[4];
            ldm4(af, &smh[HACB + haoff + k0]);
#pragma unroll
            for (int nt = 0; nt < 8; nt++) {
                const __half* bp = &smh[HG + (nt * 8 + hbn) * 72 + k0 + hbk];
                mma16h(cbG[nt], af, *(const uint32_t*)bp, *(const uint32_t*)(bp + 8));
            }
            const int trow = (k0 + trow_off) * 72 + tcol_off;
#pragma unroll
            for (int ng = 0; ng < 4; ng++) {
                uint32_t mb[4];
                ldm4t(mb, &smh[HM + trow + (ng << 4)]);
                mma16h(bvv[ng * 2], af, mb[0], mb[1]);
                mma16h(bvv[ng * 2 + 1], af, mb[2], mb[3]);
            }
        }
#pragma unroll
        for (int nt = 0; nt < 8; nt++) {
            int c = nt * 8 + cbase;
            __half2 cbl0 = *(const __half2*)&smh[HACB + r0 * 72 + c];
            __half2 cbl1 = *(const __half2*)&smh[HACB + (r0 + 8) * 72 + c];
            float2 f0 = __half22float2(cbl0), f1 = __half22float2(cbl1);
            bsq0 += cbG[nt][0] * f0.x + cbG[nt][1] * f0.y;
            bsq1 += cbG[nt][2] * f1.x + cbG[nt][3] * f1.y;
        }
#pragma unroll
        for (int o = 1; o <= 2; o <<= 1) {
            bsq0 += __shfl_xor_sync(0xffffffffu, bsq0, o);
            bsq1 += __shfl_xor_sync(0xffffffffu, bsq1, o);
        }
        bsq0 = fmaxf(bsq0, 0.f);
        bsq1 = fmaxf(bsq1, 0.f);
    }

    float s0 = 0.f, s1 = 0.f, spp0 = 0.f, spp1 = 0.f;
    float pv[8][4] = {}, pc[8][4] = {};

#pragma unroll 1
    for (int kt = 0; kt < ktmax; kt++) {
        const int s = kt & 1;
        if (kt + 1 < ktmax) {
            ld_stage(kt + 1, s ^ 1);
            CPA_COMMIT();
            CPA_WAIT1();
        } else {
            CPA_WAIT0();
        }
        __syncthreads();
        const __half* stg = &smh[HBS + s * HSTG];

        float accS[8][4] = {};
#pragma unroll
        for (int kc = 0; kc < 4; kc++) {
            const int k0 = kc << 4;
            uint32_t af[4];
            ldm4(af, &smh[HAQ + haoff + k0]);
#pragma unroll
            for (int nt = 0; nt < 8; nt++) {
                const __half* bp = &stg[(nt * 8 + hbn) * 72 + k0 + hbk];
                mma16h(accS[nt], af, *(const uint32_t*)bp, *(const uint32_t*)(bp + 8));
            }
        }

        const bool part = (kt >= 2 * qt);
#pragma unroll
        for (int nt = 0; nt < 8; nt++) {
            int c0i = (kt << 6) + nt * 8 + cbase;
#pragma unroll
            for (int j = 0; j < 4; j++) {
                int colg = c0i + (j & 1);
                int rowg = (j < 2) ? qrow0 : qrow1;
                float v = accS[nt][j] * sc2;
                if (part && colg > rowg) v = -1e30f;
                accS[nt][j] = exp2f(v);
            }
            float p00 = accS[nt][0], p01 = accS[nt][1];
            float p10 = accS[nt][2], p11 = accS[nt][3];
            s0 += p00 + p01; s1 += p10 + p11;
            spp0 += p00 * p00 + p01 * p01;
            spp1 += p10 * p10 + p11 * p11;
        }

        uint32_t paf[4][4];
#pragma unroll
        for (int kc = 0; kc < 4; kc++) {
            __half2 t0 = __floats2half2_rn(accS[2 * kc][0], accS[2 * kc][1]);
            __half2 t1 = __floats2half2_rn(accS[2 * kc][2], accS[2 * kc][3]);
            __half2 t2 = __floats2half2_rn(accS[2 * kc + 1][0], accS[2 * kc + 1][1]);
            __half2 t3 = __floats2half2_rn(accS[2 * kc + 1][2], accS[2 * kc + 1][3]);
            paf[kc][0] = *(uint32_t*)&t0;
            paf[kc][1] = *(uint32_t*)&t1;
            paf[kc][2] = *(uint32_t*)&t2;
            paf[kc][3] = *(uint32_t*)&t3;
        }

#pragma unroll
        for (int kc = 0; kc < 4; kc++) {
            const int k0 = kc << 4;
            const int trow = (k0 + trow_off) * 72 + tcol_off;
#pragma unroll
            for (int ng = 0; ng < 4; ng++) {
                const int n0 = ng << 4;
                uint32_t vb[4];
                ldm4t(vb, &stg[9216 + trow + n0]);
                mma16h(pv[ng * 2], paf[kc], vb[0], vb[1]);
                mma16h(pv[ng * 2 + 1], paf[kc], vb[2], vb[3]);
                uint32_t cf[4];
                ldm4t(cf, &stg[4608 + trow + n0]);
                mma16h(pc[ng * 2], paf[kc], cf[0], cf[1]);
                mma16h(pc[ng * 2 + 1], paf[kc], cf[2], cf[3]);
            }
        }
        __syncthreads();
    }

    float spb0 = 0.f, spb1 = 0.f;
#pragma unroll
    for (int nt = 0; nt < 8; nt++) {
        int c = nt * 8 + cbase;
        __half2 cbl0 = *(const __half2*)&smh[HACB + r0 * 72 + c];
        __half2 cbl1 = *(const __half2*)&smh[HACB + (r0 + 8) * 72 + c];
        float2 f0 = __half22float2(cbl0), f1 = __half22float2(cbl1);
        spb0 += pc[nt][0] * f0.x + pc[nt][1] * f0.y;
        spb1 += pc[nt][2] * f1.x + pc[nt][3] * f1.y;
    }

#pragma unroll
    for (int o = 1; o <= 2; o <<= 1) {
        s0 += __shfl_xor_sync(0xffffffffu, s0, o);
        s1 += __shfl_xor_sync(0xffffffffu, s1, o);
        spp0 += __shfl_xor_sync(0xffffffffu, spp0, o);
        spp1 += __shfl_xor_sync(0xffffffffu, spp1, o);
        spb0 += __shfl_xor_sync(0xffffffffu, spb0, o);
        spb1 += __shfl_xor_sync(0xffffffffu, spb1, o);
    }
    float pinv0 = 1.f / s0, pinv1 = 1.f / s1;
    float bmul0 = bs / fmaxf(sqrtf(bsq0), 1e-12f);
    float bmul1 = bs / fmaxf(sqrtf(bsq1), 1e-12f);
    float csq0 = pinv0 * pinv0 * spp0 + 2.f * pinv0 * bmul0 * spb0 + bmul0 * bmul0 * bsq0;
    float csq1 = pinv1 * pinv1 * spp1 + 2.f * pinv1 * bmul1 * spb1 + bmul1 * bmul1 * bsq1;
    float cinv0 = 1.f / fmaxf(sqrtf(csq0), 1e-12f);
    float cinv1 = 1.f / fmaxf(sqrtf(csq1), 1e-12f);

    const int b = bh >> 4, h = bh & 15;
    const int l0 = (qt << 7) + r0;
#pragma unroll
    for (int nt = 0; nt < 8; nt++) {
        int dk = nt * 8 + cbase;
        float o00 = cinv0 * (pinv0 * pv[nt][0] + bmul0 * bvv[nt][0]);
        float o01 = cinv0 * (pinv0 * pv[nt][1] + bmul0 * bvv[nt][1]);
        float o10 = cinv1 * (pinv1 * pv[nt][2] + bmul1 * bvv[nt][2]);
        float o11 = cinv1 * (pinv1 * pv[nt][3] + bmul1 * bvv[nt][3]);
        *(__half2*)&g_mh[(((size_t)((b << 10) + l0)) << 10) + (h << 6) + dk] =
            __floats2half2_rn(o00, o01);
        *(__half2*)&g_mh[(((size_t)((b << 10) + l0 + 8)) << 10) + (h << 6) + dk] =
            __floats2half2_rn(o10, o11);
    }
}

// ---------------------------------------------------------------------------
extern "C" void kernel_launch(void* const* d_in, const int* in_sizes, int n_in,
                              void* d_out, int out_size)
{
    const float* Q      = (const float*)d_in[0];
    const float* ctx    = (const float*)d_in[1];
    const float* Wq     = (const float*)d_in[3];
    const float* bq     = (const float*)d_in[4];
    const float* Wk     = (const float*)d_in[5];
    const float* bk     = (const float*)d_in[6];
    const float* Wv     = (const float*)d_in[7];
    const float* bv     = (const float*)d_in[8];
    const float* bil    = (const float*)d_in[9];
    const float* gam    = (const float*)d_in[10];
    const float* bet    = (const float*)d_in[11];
    const float* scale  = (const float*)d_in[12];
    const float* bscale = (const float*)d_in[13];
    const float* Wo     = (const float*)d_in[14];
    const float* bo     = (const float*)d_in[15];
    float* out = (float*)d_out;

    static cudaStream_t s2 = nullptr;
    static cudaEvent_t evA = nullptr, evB = nullptr, evC = nullptr, evF = nullptr;
    static cudaEvent_t evP[3] = {nullptr, nullptr, nullptr};
    static int attr_set = 0;
    if (!attr_set) {
        cudaFuncSetAttribute(fused_attn, cudaFuncAttributeMaxDynamicSharedMemorySize,
                             SM_TOTAL_BYTES);
        cudaFuncSetAttribute(gemm_h<1>, cudaFuncAttributeMaxDynamicSharedMemorySize,
                             GEMM_SMEM_BYTES);
        cudaFuncSetAttribute(gemm_h<0>, cudaFuncAttributeMaxDynamicSharedMemorySize,
                             GEMM_SMEM_BYTES);
        cudaStreamCreateWithFlags(&s2, cudaStreamNonBlocking);
        cudaEventCreateWithFlags(&evA, cudaEventDisableTiming);
        cudaEventCreateWithFlags(&evB, cudaEventDisableTiming);
        cudaEventCreateWithFlags(&evC, cudaEventDisableTiming);
        cudaEventCreateWithFlags(&evF, cudaEventDisableTiming);
        for (int i = 0; i < 3; i++)
            cudaEventCreateWithFlags(&evP[i], cudaEventDisableTiming);
        attr_set = 1;
    }

    __half* d_qin; cudaGetSymbolAddress((void**)&d_qin, g_qin_h);
    __half* d_mh;  cudaGetSymbolAddress((void**)&d_mh, g_mh);

    // fork s2: ln overlaps QKV GEMM
    cudaEventRecord(evA, 0);
    cudaStreamWaitEvent(s2, evA, 0);
    ln_bilinear_kernel<<<2048, 128, 0, s2>>>(ctx, bil, gam, bet);

    cvt_half<<<8192, 256>>>(Q, d_qin, 2097152);
    transpose_cvt_h4<<<dim3(32, 32, 4), 256>>>(Wq, Wk, Wv, Wo);
    gemm_h<1><<<dim3(8, 64, 3), 256, GEMM_SMEM_BYTES>>>(d_qin, bq, bk, bv, nullptr, 0);
    cudaEventRecord(evB, 0);

    cudaStreamWaitEvent(s2, evB, 0);
    gram_kernel<<<128, 256, 0, s2>>>();
    cudaEventRecord(evC, s2);

    cudaStreamWaitEvent(0, evC, 0);

    // 4-stage attn/out-proj pipeline: attn chunk i (32 bh = batches 2i..2i+1)
    // -> out-proj rows i*2048..+2047 (ybase = i*16) on s2.
    for (int i = 0; i < 4; i++) {
        fused_attn<<<dim3(8, 32), 256, SM_TOTAL_BYTES>>>(scale, bscale, i * 32);
        if (i < 3) {
            cudaEventRecord(evP[i], 0);
            cudaStreamWaitEvent(s2, evP[i], 0);
            gemm_h<0><<<dim3(8, 16), 256, GEMM_SMEM_BYTES, s2>>>(
                d_mh, bo, nullptr, nullptr, out, i * 16);
            if (i == 2) cudaEventRecord(evF, s2);
        }
    }
    // final out-proj chunk on main, then join s2
    gemm_h<0><<<dim3(8, 16), 256, GEMM_SMEM_BYTES>>>(d_mh, bo, nullptr, nullptr, out, 48);
    cudaStreamWaitEvent(0, evF, 0);
}

// round 17
// speedup vs baseline: 1.1428x; 1.1428x over previous
#include <cuda_runtime.h>
#include <cuda_fp16.h>
#include <math.h>
#include <stdint.h>

// ---------------------------------------------------------------------------
// B=8, L=1024, D=1024, H=16, DK=64  (BH=128, M=8192)
// fp16 m16n8k16 everywhere. Rank-64 bias (G=C^T C, M=C^T V) fp16.
// Max-free softmax (scores bounded). p passed mma->mma via register repack
// (score C-frag == p A-frag). attn split by batch-half; out-proj overlapped.
// (R15 configuration — the 4-way chunking of R16 regressed and is reverted.)
// ---------------------------------------------------------------------------
__device__ __half g_qin_h[8388608];
__device__ __half g_wqt_h[1048576];
__device__ __half g_wkt_h[1048576];
__device__ __half g_wvt_h[1048576];
__device__ __half g_wot_h[1048576];
__device__ __half g_qh[8388608];
__device__ __half g_kh[8388608];
__device__ __half g_vh[8388608];
__device__ __half g_ch[8388608];
__device__ __half g_cbh[8388608];
__device__ __half g_mh[8388608];
__device__ __half g_Gh[524288];
__device__ __half g_Mh[524288];

// ---------------------------------------------------------------------------
__device__ __forceinline__ uint32_t f2tf(float f) {
    uint32_t r; asm("cvt.rna.tf32.f32 %0, %1;" : "=r"(r) : "f"(f)); return r;
}
__device__ __forceinline__ void ldm4(uint32_t* r, const void* p) {
    uint32_t a = (uint32_t)__cvta_generic_to_shared(p);
    asm volatile("ldmatrix.sync.aligned.m8n8.x4.shared.b16 {%0,%1,%2,%3}, [%4];"
        : "=r"(r[0]), "=r"(r[1]), "=r"(r[2]), "=r"(r[3]) : "r"(a));
}
__device__ __forceinline__ void ldm4t(uint32_t* r, const void* p) {
    uint32_t a = (uint32_t)__cvta_generic_to_shared(p);
    asm volatile("ldmatrix.sync.aligned.m8n8.x4.trans.shared.b16 {%0,%1,%2,%3}, [%4];"
        : "=r"(r[0]), "=r"(r[1]), "=r"(r[2]), "=r"(r[3]) : "r"(a));
}
__device__ __forceinline__ void mma8(float* c, const uint32_t* a, uint32_t b0, uint32_t b1) {
    asm volatile("mma.sync.aligned.m16n8k8.row.col.f32.tf32.tf32.f32 "
        "{%0,%1,%2,%3},{%4,%5,%6,%7},{%8,%9},{%0,%1,%2,%3};"
        : "+f"(c[0]), "+f"(c[1]), "+f"(c[2]), "+f"(c[3])
        : "r"(a[0]), "r"(a[1]), "r"(a[2]), "r"(a[3]), "r"(b0), "r"(b1));
}
__device__ __forceinline__ void mma16h(float* c, const uint32_t* a, uint32_t b0, uint32_t b1) {
    asm volatile("mma.sync.aligned.m16n8k16.row.col.f32.f16.f16.f32 "
        "{%0,%1,%2,%3},{%4,%5,%6,%7},{%8,%9},{%0,%1,%2,%3};"
        : "+f"(c[0]), "+f"(c[1]), "+f"(c[2]), "+f"(c[3])
        : "r"(a[0]), "r"(a[1]), "r"(a[2]), "r"(a[3]), "r"(b0), "r"(b1));
}
__device__ __forceinline__ void cpa16(void* s, const void* g) {
    uint32_t a = (uint32_t)__cvta_generic_to_shared(s);
    asm volatile("cp.async.cg.shared.global [%0], [%1], 16;" :: "r"(a), "l"(g));
}
#define CPA_COMMIT() asm volatile("cp.async.commit_group;" ::: "memory")
#define CPA_WAIT1()  asm volatile("cp.async.wait_group 1;" ::: "memory")
#define CPA_WAIT0()  asm volatile("cp.async.wait_group 0;" ::: "memory")

// ---------------------------------------------------------------------------
__global__ __launch_bounds__(256) void cvt_half(
    const float* __restrict__ src, __half* __restrict__ dst, int n4)
{
    int i = blockIdx.x * 256 + threadIdx.x;
    if (i < n4) {
        float4 v = ((const float4*)src)[i];
        __half2 a = __floats2half2_rn(v.x, v.y);
        __half2 b = __floats2half2_rn(v.z, v.w);
        uint2 o;
        o.x = *(uint32_t*)&a; o.y = *(uint32_t*)&b;
        *(uint2*)(dst + (size_t)i * 4) = o;
    }
}
__global__ __launch_bounds__(256) void transpose_cvt_h4(
    const float* __restrict__ s0, const float* __restrict__ s1,
    const float* __restrict__ s2, const float* __restrict__ s3)
{
    __shared__ float t[32][33];
    const int z = blockIdx.z;
    const float* src = (z == 0) ? s0 : (z == 1) ? s1 : (z == 2) ? s2 : s3;
    __half* dst = (z == 0) ? g_wqt_h : (z == 1) ? g_wkt_h : (z == 2) ? g_wvt_h : g_wot_h;
    int bk = blockIdx.x << 5, bn = blockIdx.y << 5;
    int x = threadIdx.x & 31, y = threadIdx.x >> 5;
#pragma unroll
    for (int j = 0; j < 32; j += 8)
        t[y + j][x] = src[(size_t)(bk + y + j) * 1024 + bn + x];
    __syncthreads();
#pragma unroll
    for (int j = 0; j < 32; j += 8)
        dst[(size_t)(bn + y + j) * 1024 + bk + x] = __float2half_rn(t[x][y + j]);
}

// ---------------------------------------------------------------------------
// fp16 GEMM 128x128xBK32 (m16n8k16), cp.async 3-stage pipeline.
// QKV=1: merged QKV (z selects). QKV=0: out-proj rows offset by ybase tiles.
// ---------------------------------------------------------------------------
#define GEMM_SMEM_BYTES 61440

template <int QKV>
__global__ __launch_bounds__(256) void gemm_h(
    const __half* __restrict__ A,
    const float* __restrict__ bias_q, const float* __restrict__ bias_k,
    const float* __restrict__ bias_v, float* __restrict__ Cout, int ybase)
{
    extern __shared__ __half gsm[];

    const int tid = threadIdx.x;
    const int lane = tid & 31, w = tid >> 5;
    const int r0 = (blockIdx.y + ybase) << 7, c0 = blockIdx.x << 7;
    const int dst = QKV ? (int)blockIdx.z : 3;
    const __half* Wt = QKV
        ? ((dst == 0) ? g_wqt_h : (dst == 1) ? g_wkt_h : g_wvt_h)
        : g_wot_h;
    const float* bias = QKV
        ? ((dst == 0) ? bias_q : (dst == 1) ? bias_k : bias_v)
        : bias_q;

    const int mwarp = (w >> 2) * 64, nwarp = (w & 3) * 32;
    const int lrow = lane & 15;
    const int lcol8 = (lane >> 4) << 3;
    const int bn_ = lane >> 2;
    const int bk_ = (lane & 3) << 1;

    const int ld_row0 = tid >> 2, ld_off = (tid & 3) << 3;
    const int ld_row1 = (tid + 256) >> 2;

    float acc[4][4][4] = {};

    auto ld_stage = [&](int kt, int s) {
        __half* As = &gsm[s * 10240];
        __half* Bs = As + 5120;
        const __half* ag = A + (size_t)r0 * 1024 + (kt << 5);
        const __half* bg = Wt + (size_t)c0 * 1024 + (kt << 5);
        cpa16(&As[ld_row0 * 40 + ld_off], ag + (size_t)ld_row0 * 1024 + ld_off);
        cpa16(&As[ld_row1 * 40 + ld_off], ag + (size_t)ld_row1 * 1024 + ld_off);
        cpa16(&Bs[ld_row0 * 40 + ld_off], bg + (size_t)ld_row0 * 1024 + ld_off);
        cpa16(&Bs[ld_row1 * 40 + ld_off], bg + (size_t)ld_row1 * 1024 + ld_off);
    };

    ld_stage(0, 0); CPA_COMMIT();
    ld_stage(1, 1); CPA_COMMIT();

#pragma unroll 1
    for (int kt = 0; kt < 32; kt++) {
        if (kt + 2 < 32) { CPA_WAIT1(); } else { CPA_WAIT0(); }
        __syncthreads();
        if (kt + 2 < 32) { ld_stage(kt + 2, (kt + 2) % 3); CPA_COMMIT(); }

        const __half* As = &gsm[(kt % 3) * 10240];
        const __half* Bs = As + 5120;
#pragma unroll
        for (int ks = 0; ks < 2; ks++) {
            const int kof = ks << 4;
            uint32_t afr[4][4];
#pragma unroll
            for (int mt = 0; mt < 4; mt++)
                ldm4(afr[mt], &As[(mwarp + mt * 16 + lrow) * 40 + kof + lcol8]);
            uint32_t b0r[4], b1r[4];
#pragma unroll
            for (int nt = 0; nt < 4; nt++) {
                const __half* bp = &Bs[(nwarp + nt * 8 + bn_) * 40 + kof + bk_];
                b0r[nt] = *(const uint32_t*)bp;
                b1r[nt] = *(const uint32_t*)(bp + 8);
            }
#pragma unroll
            for (int mt = 0; mt < 4; mt++)
#pragma unroll
                for (int nt = 0; nt < 4; nt++)
                    mma16h(acc[mt][nt], afr[mt], b0r[nt], b1r[nt]);
        }
    }

    __half* Hsplit = (dst == 0) ? g_qh : (dst == 1) ? g_kh : g_vh;
    const int rl = lane >> 2, cl = (lane & 3) << 1;
#pragma unroll
    for (int mt = 0; mt < 4; mt++)
#pragma unroll
        for (int nt = 0; nt < 4; nt++) {
            int row = r0 + mwarp + mt * 16 + rl;
            int col = c0 + nwarp + nt * 8 + cl;
            float bv0 = bias[col], bv1 = bias[col + 1];
            float v00 = acc[mt][nt][0] + bv0, v01 = acc[mt][nt][1] + bv1;
            float v10 = acc[mt][nt][2] + bv0, v11 = acc[mt][nt][3] + bv1;
            if (QKV) {
                int h = col >> 6, dk = col & 63;
                int b0i = row >> 10, l0 = row & 1023;
                int b1i = (row + 8) >> 10, l1 = (row + 8) & 1023;
                size_t i0 = (((size_t)((b0i << 4) + h)) << 16) + ((size_t)l0 << 6) + dk;
                size_t i1 = (((size_t)((b1i << 4) + h)) << 16) + ((size_t)l1 << 6) + dk;
                *(__half2*)&Hsplit[i0] = __floats2half2_rn(v00, v01);
                *(__half2*)&Hsplit[i1] = __floats2half2_rn(v10, v11);
            } else {
                *(float2*)&Cout[(size_t)row * 1024 + col] = make_float2(v00, v01);
                *(float2*)&Cout[(size_t)(row + 8) * 1024 + col] = make_float2(v10, v11);
            }
        }
}

// ---------------------------------------------------------------------------
// LayerNorm(ctx -> heads) -> g_ch (half) ; g_cbh via tf32 mma.
// ---------------------------------------------------------------------------
__global__ __launch_bounds__(128) void ln_bilinear_kernel(
    const float* __restrict__ ctx, const float* __restrict__ bil,
    const float* __restrict__ gamma, const float* __restrict__ beta)
{
    __shared__ uint32_t cs[64 * 68];
    __shared__ uint32_t bls[64 * 68];
    const int tid = threadIdx.x, lane = tid & 31, w = tid >> 5;

    for (int i = tid; i < 1024; i += 128) {
        int idx4 = i << 2;
        int row = idx4 >> 6, col = idx4 & 63;
        float4 v = *(const float4*)(bil + idx4);
        uint4 o;
        o.x = f2tf(v.x); o.y = f2tf(v.y); o.z = f2tf(v.z); o.w = f2tf(v.w);
        *(uint4*)&bls[row * 68 + col] = o;
    }

    const float g0 = gamma[lane], g1 = gamma[lane + 32];
    const float be0 = beta[lane], be1 = beta[lane + 32];

#pragma unroll 1
    for (int r = 0; r < 16; r++) {
        int rloc = w * 16 + r;
        int rid = blockIdx.x * 64 + rloc;
        int bh = rid >> 10, l = rid & 1023;
        int b = bh >> 4, h = bh & 15;
        const float* x = ctx + ((size_t)((b << 10) + l) << 10) + (h << 6);

        float v0 = x[lane], v1 = x[lane + 32];
        float s = v0 + v1;
#pragma unroll
        for (int o = 16; o > 0; o >>= 1) s += __shfl_xor_sync(0xffffffffu, s, o);
        float mu = s * (1.f / 64.f);
        float d0 = v0 - mu, d1 = v1 - mu;
        float vs = d0 * d0 + d1 * d1;
#pragma unroll
        for (int o = 16; o > 0; o >>= 1) vs += __shfl_xor_sync(0xffffffffu, vs, o);
        float inv = rsqrtf(vs * (1.f / 64.f) + 1e-5f);

        float c0 = d0 * inv * g0 + be0;
        float c1 = d1 * inv * g1 + be1;
        g_ch[((size_t)rid << 6) + lane] = __float2half_rn(c0);
        g_ch[((size_t)rid << 6) + lane + 32] = __float2half_rn(c1);
        cs[rloc * 68 + lane] = f2tf(c0);
        cs[rloc * 68 + lane + 32] = f2tf(c1);
    }
    __syncthreads();

    const int aoff = ((lane & 7) + ((lane >> 3) & 1) * 8) * 68 + ((lane >> 4) << 2);
    const int bV = (lane & 3) * 68 + (lane >> 2);
    float acc[8][4] = {};
#pragma unroll
    for (int k0 = 0; k0 < 64; k0 += 8) {
        uint32_t af[4];
        ldm4(af, &cs[(w * 16) * 68 + k0 + aoff]);
#pragma unroll
        for (int nt = 0; nt < 8; nt++) {
            uint32_t b0 = bls[k0 * 68 + bV + nt * 8];
            uint32_t b1 = bls[(k0 + 4) * 68 + bV + nt * 8];
            mma8(acc[nt], af, b0, b1);
        }
    }
    const int r0 = w * 16 + (lane >> 2);
    const size_t rid0 = (size_t)(blockIdx.x * 64 + r0);
    const int cbase = (lane & 3) << 1;
#pragma unroll
    for (int nt = 0; nt < 8; nt++) {
        int dk = nt * 8 + cbase;
        *(__half2*)&g_cbh[(rid0 << 6) + dk] = __floats2half2_rn(acc[nt][0], acc[nt][1]);
        *(__half2*)&g_cbh[((rid0 + 8) << 6) + dk] = __floats2half2_rn(acc[nt][2], acc[nt][3]);
    }
}

// ---------------------------------------------------------------------------
// Per-head Gram matrices (fp16): G = C^T C, M = C^T V. One block/bh.
// ---------------------------------------------------------------------------
__global__ __launch_bounds__(256) void gram_kernel()
{
    __shared__ __half cs[64 * 72];
    __shared__ __half vs[64 * 72];
    const int bh = blockIdx.x;
    const __half* cg = g_ch + ((size_t)bh << 16);
    const __half* vg = g_vh + ((size_t)bh << 16);

    const int tid = threadIdx.x, lane = tid & 31, w = tid >> 5;
    const int m0 = (w & 3) * 16, nh = (w >> 2) * 32;
    const int l8 = lane & 7, grp = lane >> 3;
    const int a_trow = ((grp >> 1) << 3) + l8;
    const int a_tcol = m0 + ((grp & 1) << 3);
    const int b_trow = ((grp & 1) << 3) + l8;
    const int b_tcol = (grp >> 1) << 3;

    float accG[4][4] = {}, accM[4][4] = {};

#pragma unroll 1
    for (int lc = 0; lc < 16; lc++) {
        __syncthreads();
#pragma unroll
        for (int t = 0; t < 2; t++) {
            int i = tid + t * 256;
            int row = i >> 3, sub = (i & 7) << 3;
            *(uint4*)&cs[row * 72 + sub] =
                *(const uint4*)(cg + ((lc << 6) + row) * 64 + sub);
            *(uint4*)&vs[row * 72 + sub] =
                *(const uint4*)(vg + ((lc << 6) + row) * 64 + sub);
        }
        __syncthreads();
#pragma unroll
        for (int kc = 0; kc < 4; kc++) {
            const int k0 = kc << 4;
            uint32_t af[4];
            ldm4t(af, &cs[(k0 + a_trow) * 72 + a_tcol]);
#pragma unroll
            for (int ng = 0; ng < 2; ng++) {
                const int n0 = nh + (ng << 4);
                uint32_t gb[4];
                ldm4t(gb, &cs[(k0 + b_trow) * 72 + n0 + b_tcol]);
                mma16h(accG[ng * 2], af, gb[0], gb[1]);
                mma16h(accG[ng * 2 + 1], af, gb[2], gb[3]);
                uint32_t mb[4];
                ldm4t(mb, &vs[(k0 + b_trow) * 72 + n0 + b_tcol]);
                mma16h(accM[ng * 2], af, mb[0], mb[1]);
                mma16h(accM[ng * 2 + 1], af, mb[2], mb[3]);
            }
        }
    }

    __half* Gg = g_Gh + (bh << 12);
    __half* Mg = g_Mh + (bh << 12);
    const int rl = lane >> 2, cl = (lane & 3) << 1;
#pragma unroll
    for (int nt = 0; nt < 4; nt++) {
        int row = m0 + rl, col = nh + nt * 8 + cl;
        *(__half2*)&Gg[row * 64 + col] = __floats2half2_rn(accG[nt][0], accG[nt][1]);
        *(__half2*)&Gg[(row + 8) * 64 + col] = __floats2half2_rn(accG[nt][2], accG[nt][3]);
        *(__half2*)&Mg[row * 64 + col] = __floats2half2_rn(accM[nt][0], accM[nt][1]);
        *(__half2*)&Mg[(row + 8) * 64 + col] = __floats2half2_rn(accM[nt][2], accM[nt][3]);
    }
}

// ---------------------------------------------------------------------------
// Fused attention: fp16, cp.async double-buffered, max-free softmax,
// register-direct p repack (score C-frag -> p A-frag, no smem staging).
// ---------------------------------------------------------------------------
#define HAQ   0
#define HACB  9216
#define HG    18432
#define HM    23040
#define HBS   27648
#define HSTG  13824
#define H_TOT 55296
#define SM_TOTAL_BYTES (H_TOT * 2)   // 110592

__global__ __launch_bounds__(256) void fused_attn(
    const float* __restrict__ scale_p, const float* __restrict__ bscale_p, int bh0)
{
    extern __shared__ __half smh[];

    const int qt = (int)(gridDim.x - 1 - blockIdx.x);
    const int bh = bh0 + blockIdx.y;
    const int tid = threadIdx.x, lane = tid & 31, w = tid >> 5;

    const __half* qg = g_qh + ((size_t)bh << 16) + ((size_t)(qt << 7) << 6);
    const __half* cbg = g_cbh + ((size_t)bh << 16) + ((size_t)(qt << 7) << 6);
    const __half* kg = g_kh + ((size_t)bh << 16);
    const __half* cg = g_ch + ((size_t)bh << 16);
    const __half* vg = g_vh + ((size_t)bh << 16);
    const __half* Gg = g_Gh + (bh << 12);
    const __half* Mg = g_Mh + (bh << 12);

    const float sc2 = (*scale_p) * 1.4426950408889634f;
    const float bs = *bscale_p;
    const int ktmax = 2 * qt + 2;

    auto ld_stage = [&](int kt, int s) {
        __half* base = &smh[HBS + s * HSTG];
#pragma unroll
        for (int t = 0; t < 2; t++) {
            int i = tid + t * 256;
            int key = i >> 3, sub = (i & 7) << 3;
            cpa16(&base[key * 72 + sub], kg + ((kt << 6) + key) * 64 + sub);
            cpa16(&base[4608 + key * 72 + sub], cg + ((kt << 6) + key) * 64 + sub);
            cpa16(&base[9216 + key * 72 + sub], vg + ((kt << 6) + key) * 64 + sub);
        }
    };

    ld_stage(0, 0);
    CPA_COMMIT();

#pragma unroll
    for (int t = 0; t < 4; t++) {
        int i = tid + t * 256;
        int row = i >> 3, sub = (i & 7) << 3;
        *(uint4*)&smh[HAQ + row * 72 + sub] = *(const uint4*)(qg + row * 64 + sub);
    }
#pragma unroll
    for (int t = 0; t < 4; t++) {
        int i = tid + t * 256;
        int row = i >> 3, sub = (i & 7) << 3;
        *(uint4*)&smh[HACB + row * 72 + sub] = *(const uint4*)(cbg + row * 64 + sub);
    }
#pragma unroll
    for (int t = 0; t < 2; t++) {
        int i = tid + t * 256;
        int row = i >> 3, sub = (i & 7) << 3;
        *(uint4*)&smh[HG + row * 72 + sub] = *(const uint4*)(Gg + row * 64 + sub);
        *(uint4*)&smh[HM + row * 72 + sub] = *(const uint4*)(Mg + row * 64 + sub);
    }
    __syncthreads();

    const int r0 = w * 16 + (lane >> 2);
    const int qrow0 = (qt << 7) + r0;
    const int qrow1 = qrow0 + 8;
    const int cbase = (lane & 3) << 1;

    const int haoff = (w * 16 + (lane & 15)) * 72 + ((lane >> 4) << 3);
    const int hbn = lane >> 2;
    const int hbk = (lane & 3) << 1;
    const int l8 = lane & 7, grp = lane >> 3;
    const int trow_off = ((grp & 1) << 3) + l8;
    const int tcol_off = (grp >> 1) << 3;

    float bvv[8][4] = {};
    float bsq0 = 0.f, bsq1 = 0.f;
    {
        float cbG[8][4] = {};
#pragma unroll
        for (int kc = 0; kc < 4; kc++) {
            const int k0 = kc << 4;
            uint32_t af[4];
            ldm4(af, &smh[HACB + haoff + k0]);
#pragma unroll
            for (int nt = 0; nt < 8; nt++) {
                const __half* bp = &smh[HG + (nt * 8 + hbn) * 72 + k0 + hbk];
                mma16h(cbG[nt], af, *(const uint32_t*)bp, *(const uint32_t*)(bp + 8));
            }
            const int trow = (k0 + trow_off) * 72 + tcol_off;
#pragma unroll
            for (int ng = 0; ng < 4; ng++) {
                uint32_t mb[4];
                ldm4t(mb, &smh[HM + trow + (ng << 4)]);
                mma16h(bvv[ng * 2], af, mb[0], mb[1]);
                mma16h(bvv[ng * 2 + 1], af, mb[2], mb[3]);
            }
        }
#pragma unroll
        for (int nt = 0; nt < 8; nt++) {
            int c = nt * 8 + cbase;
            __half2 cbl0 = *(const __half2*)&smh[HACB + r0 * 72 + c];
            __half2 cbl1 = *(const __half2*)&smh[HACB + (r0 + 8) * 72 + c];
            float2 f0 = __half22float2(cbl0), f1 = __half22float2(cbl1);
            bsq0 += cbG[nt][0] * f0.x + cbG[nt][1] * f0.y;
            bsq1 += cbG[nt][2] * f1.x + cbG[nt][3] * f1.y;
        }
#pragma unroll
        for (int o = 1; o <= 2; o <<= 1) {
            bsq0 += __shfl_xor_sync(0xffffffffu, bsq0, o);
            bsq1 += __shfl_xor_sync(0xffffffffu, bsq1, o);
        }
        bsq0 = fmaxf(bsq0, 0.f);
        bsq1 = fmaxf(bsq1, 0.f);
    }

    float s0 = 0.f, s1 = 0.f, spp0 = 0.f, spp1 = 0.f;
    float pv[8][4] = {}, pc[8][4] = {};

#pragma unroll 1
    for (int kt = 0; kt < ktmax; kt++) {
        const int s = kt & 1;
        if (kt + 1 < ktmax) {
            ld_stage(kt + 1, s ^ 1);
            CPA_COMMIT();
            CPA_WAIT1();
        } else {
            CPA_WAIT0();
        }
        __syncthreads();
        const __half* stg = &smh[HBS + s * HSTG];

        float accS[8][4] = {};
#pragma unroll
        for (int kc = 0; kc < 4; kc++) {
            const int k0 = kc << 4;
            uint32_t af[4];
            ldm4(af, &smh[HAQ + haoff + k0]);
#pragma unroll
            for (int nt = 0; nt < 8; nt++) {
                const __half* bp = &stg[(nt * 8 + hbn) * 72 + k0 + hbk];
                mma16h(accS[nt], af, *(const uint32_t*)bp, *(const uint32_t*)(bp + 8));
            }
        }

        const bool part = (kt >= 2 * qt);
#pragma unroll
        for (int nt = 0; nt < 8; nt++) {
            int c0i = (kt << 6) + nt * 8 + cbase;
#pragma unroll
            for (int j = 0; j < 4; j++) {
                int colg = c0i + (j & 1);
                int rowg = (j < 2) ? qrow0 : qrow1;
                float v = accS[nt][j] * sc2;
                if (part && colg > rowg) v = -1e30f;
                accS[nt][j] = exp2f(v);
            }
            float p00 = accS[nt][0], p01 = accS[nt][1];
            float p10 = accS[nt][2], p11 = accS[nt][3];
            s0 += p00 + p01; s1 += p10 + p11;
            spp0 += p00 * p00 + p01 * p01;
            spp1 += p10 * p10 + p11 * p11;
        }

        uint32_t paf[4][4];
#pragma unroll
        for (int kc = 0; kc < 4; kc++) {
            __half2 t0 = __floats2half2_rn(accS[2 * kc][0], accS[2 * kc][1]);
            __half2 t1 = __floats2half2_rn(accS[2 * kc][2], accS[2 * kc][3]);
            __half2 t2 = __floats2half2_rn(accS[2 * kc + 1][0], accS[2 * kc + 1][1]);
            __half2 t3 = __floats2half2_rn(accS[2 * kc + 1][2], accS[2 * kc + 1][3]);
            paf[kc][0] = *(uint32_t*)&t0;
            paf[kc][1] = *(uint32_t*)&t1;
            paf[kc][2] = *(uint32_t*)&t2;
            paf[kc][3] = *(uint32_t*)&t3;
        }

#pragma unroll
        for (int kc = 0; kc < 4; kc++) {
            const int k0 = kc << 4;
            const int trow = (k0 + trow_off) * 72 + tcol_off;
#pragma unroll
            for (int ng = 0; ng < 4; ng++) {
                const int n0 = ng << 4;
                uint32_t vb[4];
                ldm4t(vb, &stg[9216 + trow + n0]);
                mma16h(pv[ng * 2], paf[kc], vb[0], vb[1]);
                mma16h(pv[ng * 2 + 1], paf[kc], vb[2], vb[3]);
                uint32_t cf[4];
                ldm4t(cf, &stg[4608 + trow + n0]);
                mma16h(pc[ng * 2], paf[kc], cf[0], cf[1]);
                mma16h(pc[ng * 2 + 1], paf[kc], cf[2], cf[3]);
            }
        }
        __syncthreads();
    }

    float spb0 = 0.f, spb1 = 0.f;
#pragma unroll
    for (int nt = 0; nt < 8; nt++) {
        int c = nt * 8 + cbase;
        __half2 cbl0 = *(const __half2*)&smh[HACB + r0 * 72 + c];
        __half2 cbl1 = *(const __half2*)&smh[HACB + (r0 + 8) * 72 + c];
        float2 f0 = __half22float2(cbl0), f1 = __half22float2(cbl1);
        spb0 += pc[nt][0] * f0.x + pc[nt][1] * f0.y;
        spb1 += pc[nt][2] * f1.x + pc[nt][3] * f1.y;
    }

#pragma unroll
    for (int o = 1; o <= 2; o <<= 1) {
        s0 += __shfl_xor_sync(0xffffffffu, s0, o);
        s1 += __shfl_xor_sync(0xffffffffu, s1, o);
        spp0 += __shfl_xor_sync(0xffffffffu, spp0, o);
        spp1 += __shfl_xor_sync(0xffffffffu, spp1, o);
        spb0 += __shfl_xor_sync(0xffffffffu, spb0, o);
        spb1 += __shfl_xor_sync(0xffffffffu, spb1, o);
    }
    float pinv0 = 1.f / s0, pinv1 = 1.f / s1;
    float bmul0 = bs / fmaxf(sqrtf(bsq0), 1e-12f);
    float bmul1 = bs / fmaxf(sqrtf(bsq1), 1e-12f);
    float csq0 = pinv0 * pinv0 * spp0 + 2.f * pinv0 * bmul0 * spb0 + bmul0 * bmul0 * bsq0;
    float csq1 = pinv1 * pinv1 * spp1 + 2.f * pinv1 * bmul1 * spb1 + bmul1 * bmul1 * bsq1;
    float cinv0 = 1.f / fmaxf(sqrtf(csq0), 1e-12f);
    float cinv1 = 1.f / fmaxf(sqrtf(csq1), 1e-12f);

    const int b = bh >> 4, h = bh & 15;
    const int l0 = (qt << 7) + r0;
#pragma unroll
    for (int nt = 0; nt < 8; nt++) {
        int dk = nt * 8 + cbase;
        float o00 = cinv0 * (pinv0 * pv[nt][0] + bmul0 * bvv[nt][0]);
        float o01 = cinv0 * (pinv0 * pv[nt][1] + bmul0 * bvv[nt][1]);
        float o10 = cinv1 * (pinv1 * pv[nt][2] + bmul1 * bvv[nt][2]);
        float o11 = cinv1 * (pinv1 * pv[nt][3] + bmul1 * bvv[nt][3]);
        *(__half2*)&g_mh[(((size_t)((b << 10) + l0)) << 10) + (h << 6) + dk] =
            __floats2half2_rn(o00, o01);
        *(__half2*)&g_mh[(((size_t)((b << 10) + l0 + 8)) << 10) + (h << 6) + dk] =
            __floats2half2_rn(o10, o11);
    }
}

// ---------------------------------------------------------------------------
extern "C" void kernel_launch(void* const* d_in, const int* in_sizes, int n_in,
                              void* d_out, int out_size)
{
    const float* Q      = (const float*)d_in[0];
    const float* ctx    = (const float*)d_in[1];
    const float* Wq     = (const float*)d_in[3];
    const float* bq     = (const float*)d_in[4];
    const float* Wk     = (const float*)d_in[5];
    const float* bk     = (const float*)d_in[6];
    const float* Wv     = (const float*)d_in[7];
    const float* bv     = (const float*)d_in[8];
    const float* bil    = (const float*)d_in[9];
    const float* gam    = (const float*)d_in[10];
    const float* bet    = (const float*)d_in[11];
    const float* scale  = (const float*)d_in[12];
    const float* bscale = (const float*)d_in[13];
    const float* Wo     = (const float*)d_in[14];
    const float* bo     = (const float*)d_in[15];
    float* out = (float*)d_out;

    static cudaStream_t s2 = nullptr;
    static cudaEvent_t evA = nullptr, evB = nullptr, evC = nullptr,
                       evD = nullptr, evF = nullptr;
    static int attr_set = 0;
    if (!attr_set) {
        cudaFuncSetAttribute(fused_attn, cudaFuncAttributeMaxDynamicSharedMemorySize,
                             SM_TOTAL_BYTES);
        cudaFuncSetAttribute(gemm_h<1>, cudaFuncAttributeMaxDynamicSharedMemorySize,
                             GEMM_SMEM_BYTES);
        cudaFuncSetAttribute(gemm_h<0>, cudaFuncAttributeMaxDynamicSharedMemorySize,
                             GEMM_SMEM_BYTES);
        cudaStreamCreateWithFlags(&s2, cudaStreamNonBlocking);
        cudaEventCreateWithFlags(&evA, cudaEventDisableTiming);
        cudaEventCreateWithFlags(&evB, cudaEventDisableTiming);
        cudaEventCreateWithFlags(&evC, cudaEventDisableTiming);
        cudaEventCreateWithFlags(&evD, cudaEventDisableTiming);
        cudaEventCreateWithFlags(&evF, cudaEventDisableTiming);
        attr_set = 1;
    }

    __half* d_qin; cudaGetSymbolAddress((void**)&d_qin, g_qin_h);
    __half* d_mh;  cudaGetSymbolAddress((void**)&d_mh, g_mh);

    // fork s2: ln overlaps QKV GEMM
    cudaEventRecord(evA, 0);
    cudaStreamWaitEvent(s2, evA, 0);
    ln_bilinear_kernel<<<2048, 128, 0, s2>>>(ctx, bil, gam, bet);

    cvt_half<<<8192, 256>>>(Q, d_qin, 2097152);
    transpose_cvt_h4<<<dim3(32, 32, 4), 256>>>(Wq, Wk, Wv, Wo);
    gemm_h<1><<<dim3(8, 64, 3), 256, GEMM_SMEM_BYTES>>>(d_qin, bq, bk, bv, nullptr, 0);
    cudaEventRecord(evB, 0);

    cudaStreamWaitEvent(s2, evB, 0);
    gram_kernel<<<128, 256, 0, s2>>>();
    cudaEventRecord(evC, s2);

    cudaStreamWaitEvent(0, evC, 0);

    // attention split by batch half; out-proj A overlaps attention B
    fused_attn<<<dim3(8, 64), 256, SM_TOTAL_BYTES>>>(scale, bscale, 0);
    cudaEventRecord(evD, 0);
    fused_attn<<<dim3(8, 64), 256, SM_TOTAL_BYTES>>>(scale, bscale, 64);

    cudaStreamWaitEvent(s2, evD, 0);
    gemm_h<0><<<dim3(8, 32), 256, GEMM_SMEM_BYTES, s2>>>(d_mh, bo, nullptr, nullptr, out, 0);
    cudaEventRecord(evF, s2);

    gemm_h<0><<<dim3(8, 32), 256, GEMM_SMEM_BYTES>>>(d_mh, bo, nullptr, nullptr, out, 32);
    cudaStreamWaitEvent(0, evF, 0);
}